// round 4
// baseline (speedup 1.0000x reference)
#include <cuda_runtime.h>
#include <cstdint>
#include <cstddef>

#define BB 1024
#define TT 1024
#define NN 34
#define BPB 2                      // batches per block (forward)
#define FWD_THREADS (BPB * NN)     // 68 threads
#define FWD_BLOCKS  592            // exactly 4 CTAs per SM (148*4)

// Score history: row r of batch b holds S_{r-1} (row 0 = init). [B][T+1][N]
__device__ float g_S[(size_t)BB * (TT + 1) * NN];
__device__ int g_idx[BB];

__device__ __forceinline__ unsigned long long addx2(unsigned long long a, unsigned long long b) {
    unsigned long long r;
    asm("add.rn.f32x2 %0, %1, %2;" : "=l"(r) : "l"(a), "l"(b));
    return r;
}
__device__ __forceinline__ unsigned long long packff(float f) {
    unsigned long long r; unsigned u = __float_as_uint(f);
    asm("mov.b64 %0, {%1, %1};" : "=l"(r) : "r"(u));
    return r;
}
__device__ __forceinline__ void unpk(unsigned long long v, float& lo, float& hi) {
    unsigned a, b;
    asm("mov.b64 {%0, %1}, %2;" : "=r"(a), "=r"(b) : "l"(v));
    lo = __uint_as_float(a); hi = __uint_as_float(b);
}

__global__ __launch_bounds__(FWD_THREADS)
void viterbi_fwd(const float* __restrict__ feat,
                 const float* __restrict__ trans,
                 float* __restrict__ out)
{
    const int tid = threadIdx.x;
    const int bl  = tid / NN;
    const int j   = tid % NN;
    int b = blockIdx.x * BPB + bl;
    if (b >= BB) b = BB - 1;       // tail CTAs duplicate batch 1023: identical writes, benign

    __shared__ __align__(16) float sc[2][BPB][36];
    __shared__ float tend[NN];
    __shared__ float fin[BPB][NN];

    // transition row j packed in f32x2 pairs
    unsigned long long trp[17];
#pragma unroll
    for (int i = 0; i < 17; i++) {
        unsigned lo = __float_as_uint(trans[j * NN + 2 * i]);
        unsigned hi = __float_as_uint(trans[j * NN + 2 * i + 1]);
        asm("mov.b64 %0, {%1, %2};" : "=l"(trp[i]) : "r"(lo), "r"(hi));
    }
    if (tid < NN) tend[tid] = trans[(NN - 1) * NN + tid];

    const float init = (j == NN - 2) ? 0.0f : -6969.0f;
    sc[0][bl][j] = init;
    g_S[((size_t)b * (TT + 1)) * NN + j] = init;
    __syncthreads();

    const size_t fbase = (size_t)b * ((size_t)TT * NN) + j;
    const float* fp = feat + fbase;
    float* sp_out = g_S + ((size_t)b * (TT + 1) + 1) * NN + j;

    // 4-deep feat prefetch ring
    float fring[4];
#pragma unroll
    for (int u = 0; u < 4; u++) fring[u] = __ldg(fp + (size_t)u * NN);
    fp += (size_t)4 * NN;

    int cur = 0;
#pragma unroll 1
    for (int tb = 0; tb < TT; tb += 4) {
#pragma unroll
        for (int u = 0; u < 4; u++) {
            const int t = tb + u;
            float f = fring[u];
            float fn = 0.0f;
            if (t + 4 < TT) fn = __ldg(fp);
            fp += NN;
            fring[u] = fn;

            const ulonglong2* sp2 = (const ulonglong2*)&sc[cur][bl][0];
            unsigned long long ff = packff(f);

            float m[NN];
#pragma unroll
            for (int i = 0; i < 8; i++) {
                ulonglong2 q = sp2[i];
                unsigned long long v0 = addx2(addx2(q.x, ff), trp[2 * i]);
                unsigned long long v1 = addx2(addx2(q.y, ff), trp[2 * i + 1]);
                unpk(v0, m[4 * i], m[4 * i + 1]);
                unpk(v1, m[4 * i + 2], m[4 * i + 3]);
            }
            {
                unsigned long long q = *(const unsigned long long*)&sc[cur][bl][32];
                unsigned long long v = addx2(addx2(q, ff), trp[16]);
                unpk(v, m[32], m[33]);
            }
#pragma unroll
            for (int s = 1; s < NN; s <<= 1)
#pragma unroll
                for (int k = 0; k + s < NN; k += (s << 1))
                    m[k] = fmaxf(m[k], m[k + s]);

            sc[cur ^ 1][bl][j] = m[0];
            *sp_out = m[0];
            sp_out += NN;
            cur ^= 1;
            __syncthreads();
        }
    }

    fin[bl][j] = sc[cur][bl][j] + tend[j];
    __syncthreads();
    if (j == 0) {
        float bm = -3.4e38f; int bi = 0;
#pragma unroll
        for (int k = 0; k < NN; k++) {
            float v = fin[bl][k];
            if (v > bm) { bm = v; bi = k; }
        }
        out[b] = bm;
        g_idx[b] = bi;
    }
}

// Backtrack by equality matching: S_t[j] is the known max; find first k with
// (S_{t-1}[k] + f_t[j]) + tr[j][k] == S_t[j]. Warp per batch.
__global__ __launch_bounds__(256)
void viterbi_back(const float* __restrict__ feat,
                  const float* __restrict__ trans,
                  float* __restrict__ out)
{
    __shared__ float tr[NN * NN];
    for (int i = threadIdx.x; i < NN * NN; i += blockDim.x) tr[i] = trans[i];
    __syncthreads();

    const int b = blockIdx.x * 8 + (threadIdx.x >> 5);
    const int l = threadIdx.x & 31;
    const unsigned FULL = 0xffffffffu;

    int j = g_idx[b];
    float* path = out + BB + (size_t)b * (TT + 1);
    if (l == 0) path[TT] = (float)j;

    const float* Sbase = g_S + (size_t)b * (TT + 1) * NN;   // row r = S_{r-1}
    const float* Fbase = feat + (size_t)b * TT * NN;

    // rings indexed by row&3 / t&3
    float  Sl[4];           // S row value for state k = lane (k<32)
    float2 Sh[4];           // S row states 32,33 (broadcast)
    float  Fa[4];           // feat row, state = lane
    float2 Fh[4];           // feat row states 32,33

    // init: S rows 1024..1021, feat rows 1023..1020
#pragma unroll
    for (int u = 0; u < 4; u++) {
        int r = TT - u;                         // 1024..1021
        const float* Srow = Sbase + (size_t)r * NN;
        Sl[r & 3] = __ldg(Srow + l);
        Sh[r & 3] = *(const float2*)(Srow + 32);
        int t = TT - 1 - u;                     // 1023..1020
        const float* Frow = Fbase + (size_t)t * NN;
        Fa[t & 3] = __ldg(Frow + l);
        Fh[t & 3] = *(const float2*)(Frow + 32);
    }

#pragma unroll 1
    for (int tb = TT - 1; tb >= 0; tb -= 4) {
#pragma unroll
        for (int u = 0; u < 4; u++) {
            const int t = tb - u;
            const int sT = (t + 1) & 3;         // slot holding S row t+1  (= S_t)
            const int sC = t & 3;               // slot holding S row t    (= S_{t-1}) and feat row t

            // target = S_t[j]
            float tg1 = __shfl_sync(FULL, Sl[sT], j & 31);
            float tgt = (j < 32) ? tg1 : ((j == 32) ? Sh[sT].x : Sh[sT].y);
            // f = feat[t][j]
            float f1 = __shfl_sync(FULL, Fa[sC], j & 31);
            float f  = (j < 32) ? f1 : ((j == 32) ? Fh[sC].x : Fh[sC].y);

            // trans row j
            float  tl  = tr[j * NN + l];
            float2 thi = *(const float2*)(tr + j * NN + 32);

            float c   = (Sl[sC] + f) + tl;      // identical association to forward
            unsigned m = __ballot_sync(FULL, c == tgt);
            float c32 = (Sh[sC].x + f) + thi.x;
            float c33 = (Sh[sC].y + f) + thi.y;
            j = m ? (__ffs(m) - 1) : ((c32 == tgt) ? 32 : 33);
            if (l == 0) path[t] = (float)j;

            // refill: S row t-3 -> slot (t-3)&3 == sT ; feat row t-4 -> slot sC
            int rs = t - 3; if (rs < 0) rs = 0;
            const float* Srow = Sbase + (size_t)rs * NN;
            Sl[sT] = __ldg(Srow + l);
            Sh[sT] = *(const float2*)(Srow + 32);
            int rf = t - 4; if (rf < 0) rf = 0;
            const float* Frow = Fbase + (size_t)rf * NN;
            Fa[sC] = __ldg(Frow + l);
            Fh[sC] = *(const float2*)(Frow + 32);
        }
    }
}

extern "C" void kernel_launch(void* const* d_in, const int* in_sizes, int n_in,
                              void* d_out, int out_size)
{
    const float* feat  = (const float*)d_in[0];
    const float* trans = (const float*)d_in[1];
    if (n_in >= 2 && in_sizes[0] == NN * NN) {
        feat  = (const float*)d_in[1];
        trans = (const float*)d_in[0];
    }
    float* out = (float*)d_out;

    viterbi_fwd<<<FWD_BLOCKS, FWD_THREADS>>>(feat, trans, out);
    viterbi_back<<<BB / 8, 256>>>(feat, trans, out);
}